// round 2
// baseline (speedup 1.0000x reference)
#include <cuda_runtime.h>
#include <math.h>

// Problem constants
#define B_SZ   32
#define S_SZ   1024
#define N_DIM  1024   // ATTN_DIM
#define K_DIM  1024   // 2*ENC_HID (= DEC_HID for the dec projection too)
#define M_TOT  (B_SZ * S_SZ)

// Scratch (no allocations allowed in kernel_launch)
__device__ float g_decproj[B_SZ * N_DIM];
__device__ float g_logits[B_SZ * S_SZ];

// ---- packed f32x2 helpers (FFMA2 path: 2x fp32 throughput vs 3-reg FFMA) ----
static __device__ __forceinline__ unsigned long long pk2(float lo, float hi) {
    unsigned long long r;
    asm("mov.b64 %0, {%1, %2};" : "=l"(r) : "f"(lo), "f"(hi));
    return r;
}
static __device__ __forceinline__ void upk2(unsigned long long x, float& lo, float& hi) {
    asm("mov.b64 {%0, %1}, %2;" : "=f"(lo), "=f"(hi) : "l"(x));
}
static __device__ __forceinline__ void ffma2(unsigned long long& d,
                                             unsigned long long a,
                                             unsigned long long b) {
    asm("fma.rn.f32x2 %0, %1, %2, %0;" : "+l"(d) : "l"(a), "l"(b));
}

// ---------------------------------------------------------------------------
// Kernel 1: dec_proj[b][n] = sum_k dh[b][k] * W[k][n] + bias[n]   (W rows 0..1023)
// grid (8, 32), 128 threads. Tiny (67 MFLOP); W slice stays L2-resident.
// ---------------------------------------------------------------------------
__global__ void __launch_bounds__(128) decproj_kernel(
    const float* __restrict__ dh, const float* __restrict__ W,
    const float* __restrict__ bias)
{
    const int b = blockIdx.y;
    const int n = blockIdx.x * 128 + threadIdx.x;
    __shared__ float sh[K_DIM];
    for (int i = threadIdx.x; i < K_DIM; i += 128) sh[i] = dh[b * K_DIM + i];
    __syncthreads();

    float a0 = 0.f, a1 = 0.f, a2 = 0.f, a3 = 0.f;
#pragma unroll 4
    for (int k = 0; k < K_DIM; k += 4) {
        a0 += sh[k + 0] * W[(size_t)(k + 0) * N_DIM + n];
        a1 += sh[k + 1] * W[(size_t)(k + 1) * N_DIM + n];
        a2 += sh[k + 2] * W[(size_t)(k + 2) * N_DIM + n];
        a3 += sh[k + 3] * W[(size_t)(k + 3) * N_DIM + n];
    }
    g_decproj[b * N_DIM + n] = a0 + a1 + a2 + a3 + bias[n];
}

// ---------------------------------------------------------------------------
// Kernel 2 (dominant): fused  logits[m] = sum_n tanh(Enc@Wenc [m][n] + dec[b][n]) * v[n]
//   M=32768, N=1024, K=1024.  128x128 tile, BK=8, 256 threads, 8x8/thread,
//   packed-f32x2 inner product, fused tanh+v epilogue per n-tile (enc_proj
//   never hits memory). One block spans one batch (128 | 1024).
// ---------------------------------------------------------------------------
__global__ void __launch_bounds__(256) fused_energy_kernel(
    const float* __restrict__ enc, const float* __restrict__ W,
    const float* __restrict__ v)
{
    __shared__ float As[8][132];      // [k][row], padded (132*4 % 16 == 0)
    __shared__ float Bs[8][128];      // [k][col]
    __shared__ float red[128][17];    // final cross-thread row reduction

    const int tid = threadIdx.x;
    const int tx  = tid & 15;
    const int ty  = tid >> 4;
    const int m0  = blockIdx.x * 128;
    const int b   = m0 >> 10;         // 128 | 1024 => single batch per block
    const int r0  = ty * 8;
    const int c0  = tx * 8;

    const float* __restrict__ Wenc = W + (size_t)1024 * N_DIM;  // W rows 1024..2047

    // global-load assignments
    const int lrow = tid >> 1;            // A tile: 128 rows x 8 k
    const int lk   = (tid & 1) * 4;
    const int bkr  = tid >> 5;            // B tile: 8 k x 128 n
    const int bn   = (tid & 31) * 4;

    const float* aGlob = enc + (size_t)(m0 + lrow) * K_DIM + lk;

    float rowsum[8] = {0.f, 0.f, 0.f, 0.f, 0.f, 0.f, 0.f, 0.f};

    for (int n0 = 0; n0 < N_DIM; n0 += 128) {
        unsigned long long acc[8][4];
#pragma unroll
        for (int i = 0; i < 8; ++i)
#pragma unroll
            for (int j = 0; j < 4; ++j) acc[i][j] = 0ull;

        // prefetch first k-tile
        float4 aNext = *(const float4*)(aGlob);
        float4 bNext = *(const float4*)(Wenc + (size_t)bkr * N_DIM + n0 + bn);

        for (int k0 = 0; k0 < K_DIM; k0 += 8) {
            __syncthreads();
            As[lk + 0][lrow] = aNext.x;
            As[lk + 1][lrow] = aNext.y;
            As[lk + 2][lrow] = aNext.z;
            As[lk + 3][lrow] = aNext.w;
            *(float4*)&Bs[bkr][bn] = bNext;
            __syncthreads();
            if (k0 + 8 < K_DIM) {   // prefetch next tile; overlaps with compute
                aNext = *(const float4*)(aGlob + k0 + 8);
                bNext = *(const float4*)(Wenc + (size_t)(k0 + 8 + bkr) * N_DIM + n0 + bn);
            }
#pragma unroll
            for (int kk = 0; kk < 8; ++kk) {
                float4 a0v = *(const float4*)&As[kk][r0];
                float4 a1v = *(const float4*)&As[kk][r0 + 4];
                float4 b0v = *(const float4*)&Bs[kk][c0];
                float4 b1v = *(const float4*)&Bs[kk][c0 + 4];
                // B pairs are free (adjacent cols)
                unsigned long long bp0 = pk2(b0v.x, b0v.y);
                unsigned long long bp1 = pk2(b0v.z, b0v.w);
                unsigned long long bp2 = pk2(b1v.x, b1v.y);
                unsigned long long bp3 = pk2(b1v.z, b1v.w);
                float ar[8] = {a0v.x, a0v.y, a0v.z, a0v.w,
                               a1v.x, a1v.y, a1v.z, a1v.w};
#pragma unroll
                for (int i = 0; i < 8; ++i) {
                    unsigned long long ap = pk2(ar[i], ar[i]);  // broadcast pack (ALU pipe)
                    ffma2(acc[i][0], ap, bp0);
                    ffma2(acc[i][1], ap, bp1);
                    ffma2(acc[i][2], ap, bp2);
                    ffma2(acc[i][3], ap, bp3);
                }
            }
        }

        // fused epilogue for this n-tile: tanh + dot with v, accumulate per row.
        // tanhf (accurate) on purpose: MUFU.TANH's ~6e-4 abs error accumulates to
        // ~2-3e-3 on the logits and would blow the 1e-3 rel_err gate.
        float vv[8], dd[8];
#pragma unroll
        for (int j = 0; j < 8; ++j) {
            const int n = n0 + c0 + j;
            vv[j] = v[n];
            dd[j] = g_decproj[b * N_DIM + n];
        }
#pragma unroll
        for (int i = 0; i < 8; ++i) {
#pragma unroll
            for (int jp = 0; jp < 4; ++jp) {
                float e0, e1;
                upk2(acc[i][jp], e0, e1);
                rowsum[i] += tanhf(e0 + dd[2 * jp])     * vv[2 * jp];
                rowsum[i] += tanhf(e1 + dd[2 * jp + 1]) * vv[2 * jp + 1];
            }
        }
    }

    // cross-thread reduction over the 16 tx columns
#pragma unroll
    for (int i = 0; i < 8; ++i) red[r0 + i][tx] = rowsum[i];
    __syncthreads();
    if (tid < 128) {
        float s = 0.f;
#pragma unroll
        for (int j = 0; j < 16; ++j) s += red[tid][j];
        g_logits[m0 + tid] = s;
    }
}

// ---------------------------------------------------------------------------
// Kernel 3: softmax over S per batch row. 32 blocks x 256 threads.
// ---------------------------------------------------------------------------
__global__ void __launch_bounds__(256) softmax_kernel(float* __restrict__ out)
{
    const int b = blockIdx.x, tid = threadIdx.x;
    __shared__ float sm[256];

    float vals[4];
    float m = -1e30f;
#pragma unroll
    for (int q = 0; q < 4; ++q) {
        vals[q] = g_logits[b * S_SZ + tid + 256 * q];
        m = fmaxf(m, vals[q]);
    }
    sm[tid] = m;
    __syncthreads();
    for (int s = 128; s > 0; s >>= 1) {
        if (tid < s) sm[tid] = fmaxf(sm[tid], sm[tid + s]);
        __syncthreads();
    }
    const float mx = sm[0];
    __syncthreads();

    float e[4];
    float ssum = 0.f;
#pragma unroll
    for (int q = 0; q < 4; ++q) { e[q] = expf(vals[q] - mx); ssum += e[q]; }
    sm[tid] = ssum;
    __syncthreads();
    for (int s = 128; s > 0; s >>= 1) {
        if (tid < s) sm[tid] += sm[tid + s];
        __syncthreads();
    }
    const float inv = 1.f / sm[0];
#pragma unroll
    for (int q = 0; q < 4; ++q) out[b * S_SZ + tid + 256 * q] = e[q] * inv;
}

// ---------------------------------------------------------------------------
extern "C" void kernel_launch(void* const* d_in, const int* in_sizes, int n_in,
                              void* d_out, int out_size)
{
    const float* dh   = (const float*)d_in[0];  // decoder_hidden [32,1024]
    const float* enc  = (const float*)d_in[1];  // encoder_outputs [32,1024,1024]
    const float* W    = (const float*)d_in[2];  // W [2048,1024]
    const float* bias = (const float*)d_in[3];  // b [1024]
    const float* v    = (const float*)d_in[4];  // v [1024]
    float* out = (float*)d_out;                 // [32,1024]

    decproj_kernel<<<dim3(8, 32), 128>>>(dh, W, bias);
    fused_energy_kernel<<<M_TOT / 128, 256>>>(enc, W, v);
    softmax_kernel<<<B_SZ, 256>>>(out);
}

// round 4
// speedup vs baseline: 1.7329x; 1.7329x over previous
#include <cuda_runtime.h>
#include <cuda_bf16.h>
#include <math.h>
#include <stdint.h>

// Problem constants
#define B_SZ   32
#define S_SZ   1024
#define N_DIM  1024
#define K_DIM  1024
#define M_TOT  (B_SZ * S_SZ)

// GEMM tiling
#define MT 128
#define NT 128
#define KC 64                    // k per chunk (bf16 -> 128B rows)
#define NCHUNK (K_DIM / KC)

// Scratch (__device__ globals; no allocation allowed)
__device__ float          g_decproj[B_SZ * N_DIM];
__device__ float          g_logits[B_SZ * S_SZ];
__device__ __nv_bfloat16  g_WT_hi[N_DIM * K_DIM];            // WT[n][k] = W[1024+k][n]
__device__ __nv_bfloat16  g_WT_lo[N_DIM * K_DIM];
__device__ __nv_bfloat16  g_enc_hi[(size_t)M_TOT * K_DIM];   // enc split hi
__device__ __nv_bfloat16  g_enc_lo[(size_t)M_TOT * K_DIM];   // enc split lo

// ---------------------------------------------------------------------------
// helpers
// ---------------------------------------------------------------------------
static __device__ __forceinline__ uint32_t smem_u32(const void* p) {
    uint32_t a;
    asm("{ .reg .u64 t; cvta.to.shared.u64 t, %1; cvt.u32.u64 %0, t; }" : "=r"(a) : "l"(p));
    return a;
}
static __device__ __forceinline__ uint32_t sw128(uint32_t off) {
    return off ^ ((off >> 3) & 0x70);
}
static __device__ __forceinline__ uint32_t pack_bf(__nv_bfloat16 a, __nv_bfloat16 b) {
    __nv_bfloat162 t; t.x = a; t.y = b;
    return *reinterpret_cast<uint32_t*>(&t);
}

#define CP16(dst, src) \
    asm volatile("cp.async.cg.shared.global [%0], [%1], 16;" \
                 :: "r"(dst), "l"(__cvta_generic_to_global(src)) : "memory")
#define CP_COMMIT() asm volatile("cp.async.commit_group;" ::: "memory")
#define CP_WAIT0()  asm volatile("cp.async.wait_group 0;" ::: "memory")

#define LDSM4(R, addr) \
    asm volatile("ldmatrix.sync.aligned.m8n8.x4.shared.b16 {%0,%1,%2,%3}, [%4];" \
                 : "=r"((R)[0]), "=r"((R)[1]), "=r"((R)[2]), "=r"((R)[3]) : "r"(addr))

#define MMA16816(D, A, B0, B1) \
    asm volatile("mma.sync.aligned.m16n8k16.row.col.f32.bf16.bf16.f32 " \
                 "{%0,%1,%2,%3}, {%4,%5,%6,%7}, {%8,%9}, {%0,%1,%2,%3};" \
                 : "+f"((D)[0]), "+f"((D)[1]), "+f"((D)[2]), "+f"((D)[3]) \
                 : "r"((A)[0]), "r"((A)[1]), "r"((A)[2]), "r"((A)[3]), \
                   "r"(B0), "r"(B1))

// SMEM layout (dynamic, 64 KB)
#define SA_HI 0
#define SA_LO 16384
#define SB_HI 32768
#define SB_LO 49152
#define SMEM_SZ 65536

// ---------------------------------------------------------------------------
// Prep kernels
// ---------------------------------------------------------------------------
__global__ void __launch_bounds__(256) zero_kernel() {
    int i = blockIdx.x * 256 + threadIdx.x;
    if (i < B_SZ * N_DIM) g_decproj[i] = 0.f;
    if (i < B_SZ * S_SZ)  g_logits[i]  = 0.f;
}

// enc fp32 -> bf16 hi/lo split, same [m][k] layout
__global__ void __launch_bounds__(256) prep_enc(const float* __restrict__ enc) {
    size_t i = ((size_t)blockIdx.x * 256 + threadIdx.x) * 4;
    float4 x = *(const float4*)(enc + i);
    __nv_bfloat16 hx = __float2bfloat16(x.x);
    __nv_bfloat16 hy = __float2bfloat16(x.y);
    __nv_bfloat16 hz = __float2bfloat16(x.z);
    __nv_bfloat16 hw = __float2bfloat16(x.w);
    uint2 hv, lv;
    hv.x = pack_bf(hx, hy);
    hv.y = pack_bf(hz, hw);
    lv.x = pack_bf(__float2bfloat16(x.x - __bfloat162float(hx)),
                   __float2bfloat16(x.y - __bfloat162float(hy)));
    lv.y = pack_bf(__float2bfloat16(x.z - __bfloat162float(hz)),
                   __float2bfloat16(x.w - __bfloat162float(hw)));
    *(uint2*)(g_enc_hi + i) = hv;
    *(uint2*)(g_enc_lo + i) = lv;
}

// transpose + split Wenc (W rows 1024..2047) -> WT_hi/lo [n][k]
__global__ void __launch_bounds__(256) prep_wt(const float* __restrict__ W) {
    __shared__ float tile[32][33];
    const int tx = threadIdx.x, ty = threadIdx.y;
    const int nBase = blockIdx.x * 32, kBase = blockIdx.y * 32;
#pragma unroll
    for (int i = ty; i < 32; i += 8)
        tile[i][tx] = W[(size_t)(1024 + kBase + i) * N_DIM + nBase + tx];
    __syncthreads();
#pragma unroll
    for (int i = ty; i < 32; i += 8) {
        float x = tile[tx][i];
        __nv_bfloat16 h = __float2bfloat16(x);
        size_t idx = (size_t)(nBase + i) * K_DIM + kBase + tx;
        g_WT_hi[idx] = h;
        g_WT_lo[idx] = __float2bfloat16(x - __bfloat162float(h));
    }
}

// decproj split-k: grid (8 nblk, 32 b, 8 kslice), 128 thr
__global__ void __launch_bounds__(128) decproj_kernel(
    const float* __restrict__ dh, const float* __restrict__ W,
    const float* __restrict__ bias)
{
    const int n = blockIdx.x * 128 + threadIdx.x;
    const int b = blockIdx.y;
    const int k0 = blockIdx.z * 128;
    __shared__ float sh[128];
    sh[threadIdx.x] = dh[b * K_DIM + k0 + threadIdx.x];
    __syncthreads();
    float acc = (blockIdx.z == 0) ? bias[n] : 0.f;
#pragma unroll 8
    for (int k = 0; k < 128; ++k)
        acc += sh[k] * W[(size_t)(k0 + k) * N_DIM + n];
    atomicAdd(&g_decproj[b * N_DIM + n], acc);
}

// ---------------------------------------------------------------------------
// Main: split-bf16 HMMA GEMM (mma.sync m16n8k16) + fused tanh/v epilogue.
// CTA 128x128, 8 warps in 2(m) x 4(n), warp tile 64x32, KC=64.
// Grid n-fastest so co-wave CTAs share enc tiles in L2. 2 CTAs/SM.
// ---------------------------------------------------------------------------
__global__ void __launch_bounds__(256, 2) energy_kernel(const float* __restrict__ v)
{
    extern __shared__ char smem[];
    const uint32_t sb = smem_u32(smem);
    const int tid  = threadIdx.x;
    const int lane = tid & 31;
    const int w    = tid >> 5;
    const int wm   = w >> 2;          // 0..1
    const int wn   = w & 3;           // 0..3
    const int m0   = blockIdx.y * MT;
    const int n0   = blockIdx.x * NT;
    const int b    = m0 >> 10;        // 128 | 1024

    // cp.async assignments: thread -> (row, 4 of 8 16B segs)
    const int lrow  = tid >> 1;
    const int lseg0 = (tid & 1) * 4;
    const __nv_bfloat16* aH = g_enc_hi + (size_t)(m0 + lrow) * K_DIM;
    const __nv_bfloat16* aL = g_enc_lo + (size_t)(m0 + lrow) * K_DIM;
    const __nv_bfloat16* bH = g_WT_hi + (size_t)(n0 + lrow) * K_DIM;
    const __nv_bfloat16* bL = g_WT_lo + (size_t)(n0 + lrow) * K_DIM;

    // ldmatrix lane addressing
    const int lr  = lane & 15;
    const int lkh = (lane >> 4) * 16;   // byte offset of k-half

    float acc[4][4][4];
#pragma unroll
    for (int mf = 0; mf < 4; ++mf)
#pragma unroll
        for (int nf = 0; nf < 4; ++nf)
#pragma unroll
            for (int e = 0; e < 4; ++e) acc[mf][nf][e] = 0.f;

    for (int kc = 0; kc < NCHUNK; ++kc) {
        const int k0 = kc * KC;
#pragma unroll
        for (int j = 0; j < 4; ++j) {
            const int seg = lseg0 + j;
            const uint32_t soff = sw128(lrow * 128 + seg * 16);
            const int goff = k0 + seg * 8;
            CP16(sb + SA_HI + soff, aH + goff);
            CP16(sb + SA_LO + soff, aL + goff);
            CP16(sb + SB_HI + soff, bH + goff);
            CP16(sb + SB_LO + soff, bL + goff);
        }
        CP_COMMIT();
        CP_WAIT0();
        __syncthreads();

#pragma unroll
        for (int ks = 0; ks < 4; ++ks) {
            const int kb = ks * 32 + lkh;
            uint32_t Ah[4][4], Al[4][4], Bh[2][4], Bl[2][4];
            // Ah + Bh
#pragma unroll
            for (int mf = 0; mf < 4; ++mf)
                LDSM4(Ah[mf], sb + SA_HI + sw128((wm * 64 + mf * 16 + lr) * 128 + kb));
#pragma unroll
            for (int g = 0; g < 2; ++g)
                LDSM4(Bh[g], sb + SB_HI + sw128((wn * 32 + g * 16 + lr) * 128 + kb));
            // pass hh
#pragma unroll
            for (int mf = 0; mf < 4; ++mf)
#pragma unroll
                for (int g = 0; g < 2; ++g) {
                    MMA16816(acc[mf][g * 2 + 0], Ah[mf], Bh[g][0], Bh[g][2]);
                    MMA16816(acc[mf][g * 2 + 1], Ah[mf], Bh[g][1], Bh[g][3]);
                }
            // pass hl (Ah reused)
#pragma unroll
            for (int g = 0; g < 2; ++g)
                LDSM4(Bl[g], sb + SB_LO + sw128((wn * 32 + g * 16 + lr) * 128 + kb));
#pragma unroll
            for (int mf = 0; mf < 4; ++mf)
#pragma unroll
                for (int g = 0; g < 2; ++g) {
                    MMA16816(acc[mf][g * 2 + 0], Ah[mf], Bl[g][0], Bl[g][2]);
                    MMA16816(acc[mf][g * 2 + 1], Ah[mf], Bl[g][1], Bl[g][3]);
                }
            // pass lh (Bh reused)
#pragma unroll
            for (int mf = 0; mf < 4; ++mf)
                LDSM4(Al[mf], sb + SA_LO + sw128((wm * 64 + mf * 16 + lr) * 128 + kb));
#pragma unroll
            for (int mf = 0; mf < 4; ++mf)
#pragma unroll
                for (int g = 0; g < 2; ++g) {
                    MMA16816(acc[mf][g * 2 + 0], Al[mf], Bh[g][0], Bh[g][2]);
                    MMA16816(acc[mf][g * 2 + 1], Al[mf], Bh[g][1], Bh[g][3]);
                }
        }
        __syncthreads();
    }

    // ---- epilogue: rowsum += tanh(acc + dec[n]) * v[n]; warp-reduce; atomic ----
    const int qrow = lane >> 2;
    const int qcol = (lane & 3) * 2;
    float rs[4][2];
#pragma unroll
    for (int mf = 0; mf < 4; ++mf) { rs[mf][0] = 0.f; rs[mf][1] = 0.f; }
#pragma unroll
    for (int nf = 0; nf < 4; ++nf) {
        const int col = n0 + wn * 32 + nf * 8 + qcol;
        const float v0 = v[col], v1 = v[col + 1];
        const float d0 = g_decproj[b * N_DIM + col];
        const float d1 = g_decproj[b * N_DIM + col + 1];
#pragma unroll
        for (int mf = 0; mf < 4; ++mf) {
            rs[mf][0] += tanhf(acc[mf][nf][0] + d0) * v0 + tanhf(acc[mf][nf][1] + d1) * v1;
            rs[mf][1] += tanhf(acc[mf][nf][2] + d0) * v0 + tanhf(acc[mf][nf][3] + d1) * v1;
        }
    }
#pragma unroll
    for (int mf = 0; mf < 4; ++mf)
#pragma unroll
        for (int h = 0; h < 2; ++h) {
            float s = rs[mf][h];
            s += __shfl_xor_sync(0xffffffffu, s, 1);
            s += __shfl_xor_sync(0xffffffffu, s, 2);
            if ((lane & 3) == 0)
                atomicAdd(&g_logits[m0 + wm * 64 + mf * 16 + h * 8 + qrow], s);
        }
}

// ---------------------------------------------------------------------------
// Softmax over S per batch row
// ---------------------------------------------------------------------------
__global__ void __launch_bounds__(256) softmax_kernel(float* __restrict__ out)
{
    const int b = blockIdx.x, tid = threadIdx.x;
    __shared__ float sm[256];
    float vals[4];
    float m = -1e30f;
#pragma unroll
    for (int q = 0; q < 4; ++q) {
        vals[q] = g_logits[b * S_SZ + tid + 256 * q];
        m = fmaxf(m, vals[q]);
    }
    sm[tid] = m;
    __syncthreads();
    for (int s = 128; s > 0; s >>= 1) {
        if (tid < s) sm[tid] = fmaxf(sm[tid], sm[tid + s]);
        __syncthreads();
    }
    const float mx = sm[0];
    __syncthreads();
    float e[4], ssum = 0.f;
#pragma unroll
    for (int q = 0; q < 4; ++q) { e[q] = expf(vals[q] - mx); ssum += e[q]; }
    sm[tid] = ssum;
    __syncthreads();
    for (int s = 128; s > 0; s >>= 1) {
        if (tid < s) sm[tid] += sm[tid + s];
        __syncthreads();
    }
    const float inv = 1.f / sm[0];
#pragma unroll
    for (int q = 0; q < 4; ++q) out[b * S_SZ + tid + 256 * q] = e[q] * inv;
}

// ---------------------------------------------------------------------------
extern "C" void kernel_launch(void* const* d_in, const int* in_sizes, int n_in,
                              void* d_out, int out_size)
{
    const float* dh   = (const float*)d_in[0];
    const float* enc  = (const float*)d_in[1];
    const float* W    = (const float*)d_in[2];
    const float* bias = (const float*)d_in[3];
    const float* v    = (const float*)d_in[4];
    float* out = (float*)d_out;

    cudaFuncSetAttribute(energy_kernel,
                         cudaFuncAttributeMaxDynamicSharedMemorySize, SMEM_SZ);

    zero_kernel<<<128, 256>>>();
    prep_enc<<<(int)(((size_t)M_TOT * K_DIM) / 4 / 256), 256>>>(enc);
    prep_wt<<<dim3(32, 32), dim3(32, 8)>>>(W);
    decproj_kernel<<<dim3(8, 32, 8), 128>>>(dh, W, bias);
    energy_kernel<<<dim3(N_DIM / NT, M_TOT / MT), 256, SMEM_SZ>>>(v);
    softmax_kernel<<<B_SZ, 256>>>(out);
}

// round 7
// speedup vs baseline: 1.9403x; 1.1197x over previous
#include <cuda_runtime.h>
#include <cuda_bf16.h>
#include <math.h>
#include <stdint.h>

// Problem constants
#define B_SZ   32
#define S_SZ   1024
#define N_DIM  1024
#define K_DIM  1024
#define M_TOT  (B_SZ * S_SZ)

// GEMM tiling
#define MT 128
#define NT 128
#define KC 32                       // k per chunk; hi|lo packed -> 128B rows
#define NCHUNK (K_DIM / KC)         // 32
#define NSTAGES 3

// Scratch (__device__ globals; no allocation allowed)
__device__ float          g_decproj[B_SZ * N_DIM];
__device__ float          g_logits[B_SZ * S_SZ];
__device__ __nv_bfloat16  g_WT_hi[N_DIM * K_DIM];            // WT[n][k] = W[1024+k][n]
__device__ __nv_bfloat16  g_WT_lo[N_DIM * K_DIM];
__device__ __nv_bfloat16  g_enc_hi[(size_t)M_TOT * K_DIM];
__device__ __nv_bfloat16  g_enc_lo[(size_t)M_TOT * K_DIM];

// ---------------------------------------------------------------------------
// helpers
// ---------------------------------------------------------------------------
static __device__ __forceinline__ uint32_t smem_u32(const void* p) {
    uint32_t a;
    asm("{ .reg .u64 t; cvta.to.shared.u64 t, %1; cvt.u32.u64 %0, t; }" : "=r"(a) : "l"(p));
    return a;
}
static __device__ __forceinline__ uint32_t sw128(uint32_t off) {
    return off ^ ((off >> 3) & 0x70);
}
static __device__ __forceinline__ uint32_t pack_bf(__nv_bfloat16 a, __nv_bfloat16 b) {
    __nv_bfloat162 t; t.x = a; t.y = b;
    return *reinterpret_cast<uint32_t*>(&t);
}

#define CP16(dst, src) \
    asm volatile("cp.async.cg.shared.global [%0], [%1], 16;" \
                 :: "r"(dst), "l"(__cvta_generic_to_global(src)) : "memory")
#define CP_COMMIT()  asm volatile("cp.async.commit_group;" ::: "memory")
#define CP_WAIT1()   asm volatile("cp.async.wait_group 1;" ::: "memory")
#define CP_WAIT0()   asm volatile("cp.async.wait_group 0;" ::: "memory")

#define LDSM4(R, addr) \
    asm volatile("ldmatrix.sync.aligned.m8n8.x4.shared.b16 {%0,%1,%2,%3}, [%4];" \
                 : "=r"((R)[0]), "=r"((R)[1]), "=r"((R)[2]), "=r"((R)[3]) : "r"(addr))

#define MMA16816(D, A, B0, B1) \
    asm volatile("mma.sync.aligned.m16n8k16.row.col.f32.bf16.bf16.f32 " \
                 "{%0,%1,%2,%3}, {%4,%5,%6,%7}, {%8,%9}, {%0,%1,%2,%3};" \
                 : "+f"((D)[0]), "+f"((D)[1]), "+f"((D)[2]), "+f"((D)[3]) \
                 : "r"((A)[0]), "r"((A)[1]), "r"((A)[2]), "r"((A)[3]), \
                   "r"(B0), "r"(B1))

// SMEM: per stage: A tile 16KB (rows: [Ah 64B | Al 64B]) + B tile 16KB
#define STAGE_SZ  32768
#define SA_OFF    0
#define SB_OFF    16384
#define SMEM_SZ   (NSTAGES * STAGE_SZ)   // 96 KB

// ---------------------------------------------------------------------------
// Prep kernels
// ---------------------------------------------------------------------------
__global__ void __launch_bounds__(256) zero_kernel() {
    int i = blockIdx.x * 256 + threadIdx.x;
    if (i < B_SZ * N_DIM) g_decproj[i] = 0.f;
    if (i < B_SZ * S_SZ)  g_logits[i]  = 0.f;
}

__global__ void __launch_bounds__(256) prep_enc(const float* __restrict__ enc) {
    size_t i = ((size_t)blockIdx.x * 256 + threadIdx.x) * 4;
    float4 x = *(const float4*)(enc + i);
    __nv_bfloat16 hx = __float2bfloat16(x.x);
    __nv_bfloat16 hy = __float2bfloat16(x.y);
    __nv_bfloat16 hz = __float2bfloat16(x.z);
    __nv_bfloat16 hw = __float2bfloat16(x.w);
    uint2 hv, lv;
    hv.x = pack_bf(hx, hy);
    hv.y = pack_bf(hz, hw);
    lv.x = pack_bf(__float2bfloat16(x.x - __bfloat162float(hx)),
                   __float2bfloat16(x.y - __bfloat162float(hy)));
    lv.y = pack_bf(__float2bfloat16(x.z - __bfloat162float(hz)),
                   __float2bfloat16(x.w - __bfloat162float(hw)));
    *(uint2*)(g_enc_hi + i) = hv;
    *(uint2*)(g_enc_lo + i) = lv;
}

__global__ void __launch_bounds__(256) prep_wt(const float* __restrict__ W) {
    __shared__ float tile[32][33];
    const int tx = threadIdx.x, ty = threadIdx.y;
    const int nBase = blockIdx.x * 32, kBase = blockIdx.y * 32;
#pragma unroll
    for (int i = ty; i < 32; i += 8)
        tile[i][tx] = W[(size_t)(1024 + kBase + i) * N_DIM + nBase + tx];
    __syncthreads();
#pragma unroll
    for (int i = ty; i < 32; i += 8) {
        float x = tile[tx][i];
        __nv_bfloat16 h = __float2bfloat16(x);
        size_t idx = (size_t)(nBase + i) * K_DIM + kBase + tx;
        g_WT_hi[idx] = h;
        g_WT_lo[idx] = __float2bfloat16(x - __bfloat162float(h));
    }
}

__global__ void __launch_bounds__(128) decproj_kernel(
    const float* __restrict__ dh, const float* __restrict__ W,
    const float* __restrict__ bias)
{
    const int n = blockIdx.x * 128 + threadIdx.x;
    const int b = blockIdx.y;
    const int k0 = blockIdx.z * 128;
    __shared__ float sh[128];
    sh[threadIdx.x] = dh[b * K_DIM + k0 + threadIdx.x];
    __syncthreads();
    float acc = (blockIdx.z == 0) ? bias[n] : 0.f;
#pragma unroll 8
    for (int k = 0; k < 128; ++k)
        acc += sh[k] * W[(size_t)(k0 + k) * N_DIM + n];
    atomicAdd(&g_decproj[b * N_DIM + n], acc);
}

// ---------------------------------------------------------------------------
// Main: split-bf16 HMMA GEMM, 3-stage cp.async pipeline, fused tanh/v epilogue
// CTA 128x128, 8 warps 2(m)x4(n), warp tile 64x32, KC=32, 2 CTAs/SM.
// ---------------------------------------------------------------------------
__global__ void __launch_bounds__(256, 2) energy_kernel(const float* __restrict__ v)
{
    extern __shared__ char smem[];
    const uint32_t sb = smem_u32(smem);
    const int tid  = threadIdx.x;
    const int lane = tid & 31;
    const int w    = tid >> 5;
    const int wm   = w >> 2;
    const int wn   = w & 3;
    const int m0   = blockIdx.y * MT;
    const int n0   = blockIdx.x * NT;
    const int b    = m0 >> 10;

    // copy assignments: 2 threads/row; tid&1 selects hi(bytes 0-63) or lo(64-127)
    const int lrow = tid >> 1;
    const int half = tid & 1;
    const __nv_bfloat16* aSrc = (half ? g_enc_lo : g_enc_hi) + (size_t)(m0 + lrow) * K_DIM;
    const __nv_bfloat16* bSrc = (half ? g_WT_lo : g_WT_hi) + (size_t)(n0 + lrow) * K_DIM;
    const uint32_t aDstRow = lrow * 128 + half * 64;   // pre-swizzle byte offset

    // ldmatrix lane addressing
    const int lr  = lane & 15;
    const int lkh = (lane >> 4) * 16;

    float acc[4][4][4];
#pragma unroll
    for (int mf = 0; mf < 4; ++mf)
#pragma unroll
        for (int nf = 0; nf < 4; ++nf)
#pragma unroll
            for (int e = 0; e < 4; ++e) acc[mf][nf][e] = 0.f;

#define ISSUE_CHUNK(c) do {                                                   \
    const uint32_t st = sb + ((c) % NSTAGES) * STAGE_SZ;                      \
    const int gk = (c) * KC;                                                  \
    _Pragma("unroll")                                                         \
    for (int j = 0; j < 4; ++j) {                                             \
        const uint32_t so = sw128(aDstRow + j * 16);                          \
        CP16(st + SA_OFF + so, aSrc + gk + j * 8);                            \
        CP16(st + SB_OFF + so, bSrc + gk + j * 8);                            \
    }                                                                         \
} while (0)

    // prologue: stages 0,1 in flight
    ISSUE_CHUNK(0); CP_COMMIT();
    ISSUE_CHUNK(1); CP_COMMIT();

    for (int c = 0; c < NCHUNK; ++c) {
        CP_WAIT1();
        __syncthreads();
        if (c + 2 < NCHUNK) ISSUE_CHUNK(c + 2);
        CP_COMMIT();

        const uint32_t st = sb + (c % NSTAGES) * STAGE_SZ;
#pragma unroll
        for (int ks = 0; ks < 2; ++ks) {
            const int kb = ks * 32 + lkh;
            uint32_t Ah[4][4], Al[4][4], Bh[2][4], Bl[2][4];
#pragma unroll
            for (int mf = 0; mf < 4; ++mf)
                LDSM4(Ah[mf], st + SA_OFF + sw128((wm * 64 + mf * 16 + lr) * 128 + kb));
#pragma unroll
            for (int g = 0; g < 2; ++g)
                LDSM4(Bh[g], st + SB_OFF + sw128((wn * 32 + g * 16 + lr) * 128 + kb));
            // hh
#pragma unroll
            for (int mf = 0; mf < 4; ++mf)
#pragma unroll
                for (int g = 0; g < 2; ++g) {
                    MMA16816(acc[mf][g * 2 + 0], Ah[mf], Bh[g][0], Bh[g][2]);
                    MMA16816(acc[mf][g * 2 + 1], Ah[mf], Bh[g][1], Bh[g][3]);
                }
            // hl (Ah reused)
#pragma unroll
            for (int g = 0; g < 2; ++g)
                LDSM4(Bl[g], st + SB_OFF + sw128((wn * 32 + g * 16 + lr) * 128 + 64 + kb));
#pragma unroll
            for (int mf = 0; mf < 4; ++mf)
#pragma unroll
                for (int g = 0; g < 2; ++g) {
                    MMA16816(acc[mf][g * 2 + 0], Ah[mf], Bl[g][0], Bl[g][2]);
                    MMA16816(acc[mf][g * 2 + 1], Ah[mf], Bl[g][1], Bl[g][3]);
                }
            // lh (Bh reused)
#pragma unroll
            for (int mf = 0; mf < 4; ++mf)
                LDSM4(Al[mf], st + SA_OFF + sw128((wm * 64 + mf * 16 + lr) * 128 + 64 + kb));
#pragma unroll
            for (int mf = 0; mf < 4; ++mf)
#pragma unroll
                for (int g = 0; g < 2; ++g) {
                    MMA16816(acc[mf][g * 2 + 0], Al[mf], Bh[g][0], Bh[g][2]);
                    MMA16816(acc[mf][g * 2 + 1], Al[mf], Bh[g][1], Bh[g][3]);
                }
        }
    }
#undef ISSUE_CHUNK
    CP_WAIT0();

    // ---- epilogue: rowsum += tanh(acc + dec[n]) * v[n]; warp-reduce; atomic ----
    const int qrow = lane >> 2;
    const int qcol = (lane & 3) * 2;
    float rs[4][2];
#pragma unroll
    for (int mf = 0; mf < 4; ++mf) { rs[mf][0] = 0.f; rs[mf][1] = 0.f; }
#pragma unroll
    for (int nf = 0; nf < 4; ++nf) {
        const int col = n0 + wn * 32 + nf * 8 + qcol;
        const float v0 = v[col], v1 = v[col + 1];
        const float d0 = g_decproj[b * N_DIM + col];
        const float d1 = g_decproj[b * N_DIM + col + 1];
#pragma unroll
        for (int mf = 0; mf < 4; ++mf) {
            rs[mf][0] += tanhf(acc[mf][nf][0] + d0) * v0 + tanhf(acc[mf][nf][1] + d1) * v1;
            rs[mf][1] += tanhf(acc[mf][nf][2] + d0) * v0 + tanhf(acc[mf][nf][3] + d1) * v1;
        }
    }
#pragma unroll
    for (int mf = 0; mf < 4; ++mf)
#pragma unroll
        for (int h = 0; h < 2; ++h) {
            float s = rs[mf][h];
            s += __shfl_xor_sync(0xffffffffu, s, 1);
            s += __shfl_xor_sync(0xffffffffu, s, 2);
            if ((lane & 3) == 0)
                atomicAdd(&g_logits[m0 + wm * 64 + mf * 16 + h * 8 + qrow], s);
        }
}

// ---------------------------------------------------------------------------
// Softmax over S per batch row
// ---------------------------------------------------------------------------
__global__ void __launch_bounds__(256) softmax_kernel(float* __restrict__ out)
{
    const int b = blockIdx.x, tid = threadIdx.x;
    __shared__ float sm[256];
    float vals[4];
    float m = -1e30f;
#pragma unroll
    for (int q = 0; q < 4; ++q) {
        vals[q] = g_logits[b * S_SZ + tid + 256 * q];
        m = fmaxf(m, vals[q]);
    }
    sm[tid] = m;
    __syncthreads();
    for (int s = 128; s > 0; s >>= 1) {
        if (tid < s) sm[tid] = fmaxf(sm[tid], sm[tid + s]);
        __syncthreads();
    }
    const float mx = sm[0];
    __syncthreads();
    float e[4], ssum = 0.f;
#pragma unroll
    for (int q = 0; q < 4; ++q) { e[q] = expf(vals[q] - mx); ssum += e[q]; }
    sm[tid] = ssum;
    __syncthreads();
    for (int s = 128; s > 0; s >>= 1) {
        if (tid < s) sm[tid] += sm[tid + s];
        __syncthreads();
    }
    const float inv = 1.f / sm[0];
#pragma unroll
    for (int q = 0; q < 4; ++q) out[b * S_SZ + tid + 256 * q] = e[q] * inv;
}

// ---------------------------------------------------------------------------
extern "C" void kernel_launch(void* const* d_in, const int* in_sizes, int n_in,
                              void* d_out, int out_size)
{
    const float* dh   = (const float*)d_in[0];
    const float* enc  = (const float*)d_in[1];
    const float* W    = (const float*)d_in[2];
    const float* bias = (const float*)d_in[3];
    const float* v    = (const float*)d_in[4];
    float* out = (float*)d_out;

    cudaFuncSetAttribute(energy_kernel,
                         cudaFuncAttributeMaxDynamicSharedMemorySize, SMEM_SZ);

    zero_kernel<<<128, 256>>>();
    prep_enc<<<(int)(((size_t)M_TOT * K_DIM) / 4 / 256), 256>>>(enc);
    prep_wt<<<dim3(32, 32), dim3(32, 8)>>>(W);
    decproj_kernel<<<dim3(8, 32, 8), 128>>>(dh, W, bias);
    energy_kernel<<<dim3(N_DIM / NT, M_TOT / MT), 256, SMEM_SZ>>>(v);
    softmax_kernel<<<B_SZ, 256>>>(out);
}

// round 8
// speedup vs baseline: 2.6309x; 1.3559x over previous
#include <cuda_runtime.h>
#include <cuda_bf16.h>
#include <math.h>
#include <stdint.h>

// Problem constants
#define B_SZ   32
#define S_SZ   1024
#define N_DIM  1024
#define K_DIM  1024
#define M_TOT  (B_SZ * S_SZ)

// GEMM tiling
#define MT 128
#define NT 128
#define KC 32                       // k per chunk; hi|lo packed -> 128B rows
#define NCHUNK (K_DIM / KC)         // 32
#define NSTAGES 4

// Scratch (__device__ globals; no allocation allowed)
__device__ float          g_decproj[B_SZ * N_DIM];
__device__ float          g_logits[B_SZ * S_SZ];
__device__ __nv_bfloat16  g_WT_hi[N_DIM * K_DIM];            // WT[n][k] = W[1024+k][n]
__device__ __nv_bfloat16  g_WT_lo[N_DIM * K_DIM];
__device__ __nv_bfloat16  g_enc_hi[(size_t)M_TOT * K_DIM];
__device__ __nv_bfloat16  g_enc_lo[(size_t)M_TOT * K_DIM];

// ---------------------------------------------------------------------------
// helpers
// ---------------------------------------------------------------------------
static __device__ __forceinline__ uint32_t smem_u32(const void* p) {
    uint32_t a;
    asm("{ .reg .u64 t; cvta.to.shared.u64 t, %1; cvt.u32.u64 %0, t; }" : "=r"(a) : "l"(p));
    return a;
}
static __device__ __forceinline__ uint32_t sw128(uint32_t off) {
    return off ^ ((off >> 3) & 0x70);
}
static __device__ __forceinline__ uint32_t pack_bf(__nv_bfloat16 a, __nv_bfloat16 b) {
    __nv_bfloat162 t; t.x = a; t.y = b;
    return *reinterpret_cast<uint32_t*>(&t);
}
// accurate-enough fast tanh: 1 - 2/(e^2x + 1); MUFU-based, ~1e-7 abs err,
// saturates exactly to +-1 at the extremes.
static __device__ __forceinline__ float fast_tanh(float x) {
    float e = __expf(2.f * x);
    return 1.f - __fdividef(2.f, e + 1.f);
}

#define CP16(dst, src) \
    asm volatile("cp.async.cg.shared.global [%0], [%1], 16;" \
                 :: "r"(dst), "l"(__cvta_generic_to_global(src)) : "memory")
#define CP_COMMIT()  asm volatile("cp.async.commit_group;" ::: "memory")
#define CP_WAIT2()   asm volatile("cp.async.wait_group 2;" ::: "memory")
#define CP_WAIT0()   asm volatile("cp.async.wait_group 0;" ::: "memory")

#define LDSM4(R, addr) \
    asm volatile("ldmatrix.sync.aligned.m8n8.x4.shared.b16 {%0,%1,%2,%3}, [%4];" \
                 : "=r"((R)[0]), "=r"((R)[1]), "=r"((R)[2]), "=r"((R)[3]) : "r"(addr))

#define MMA16816(D, A, B0, B1) \
    asm volatile("mma.sync.aligned.m16n8k16.row.col.f32.bf16.bf16.f32 " \
                 "{%0,%1,%2,%3}, {%4,%5,%6,%7}, {%8,%9}, {%0,%1,%2,%3};" \
                 : "+f"((D)[0]), "+f"((D)[1]), "+f"((D)[2]), "+f"((D)[3]) \
                 : "r"((A)[0]), "r"((A)[1]), "r"((A)[2]), "r"((A)[3]), \
                   "r"(B0), "r"(B1))

// SMEM: per stage: A tile 16KB (rows: [Ah 64B | Al 64B]) + B tile 16KB
#define STAGE_SZ  32768
#define SA_OFF    0
#define SB_OFF    16384
#define SMEM_SZ   (NSTAGES * STAGE_SZ)   // 128 KB

// ---------------------------------------------------------------------------
// Prep kernels
// ---------------------------------------------------------------------------
__global__ void __launch_bounds__(256) zero_kernel() {
    int i = blockIdx.x * 256 + threadIdx.x;
    if (i < B_SZ * N_DIM) g_decproj[i] = 0.f;
    if (i < B_SZ * S_SZ)  g_logits[i]  = 0.f;
}

__global__ void __launch_bounds__(256) prep_enc(const float* __restrict__ enc) {
    size_t i = ((size_t)blockIdx.x * 256 + threadIdx.x) * 4;
    float4 x = *(const float4*)(enc + i);
    __nv_bfloat16 hx = __float2bfloat16(x.x);
    __nv_bfloat16 hy = __float2bfloat16(x.y);
    __nv_bfloat16 hz = __float2bfloat16(x.z);
    __nv_bfloat16 hw = __float2bfloat16(x.w);
    uint2 hv, lv;
    hv.x = pack_bf(hx, hy);
    hv.y = pack_bf(hz, hw);
    lv.x = pack_bf(__float2bfloat16(x.x - __bfloat162float(hx)),
                   __float2bfloat16(x.y - __bfloat162float(hy)));
    lv.y = pack_bf(__float2bfloat16(x.z - __bfloat162float(hz)),
                   __float2bfloat16(x.w - __bfloat162float(hw)));
    *(uint2*)(g_enc_hi + i) = hv;
    *(uint2*)(g_enc_lo + i) = lv;
}

__global__ void __launch_bounds__(256) prep_wt(const float* __restrict__ W) {
    __shared__ float tile[32][33];
    const int tx = threadIdx.x, ty = threadIdx.y;
    const int nBase = blockIdx.x * 32, kBase = blockIdx.y * 32;
#pragma unroll
    for (int i = ty; i < 32; i += 8)
        tile[i][tx] = W[(size_t)(1024 + kBase + i) * N_DIM + nBase + tx];
    __syncthreads();
#pragma unroll
    for (int i = ty; i < 32; i += 8) {
        float x = tile[tx][i];
        __nv_bfloat16 h = __float2bfloat16(x);
        size_t idx = (size_t)(nBase + i) * K_DIM + kBase + tx;
        g_WT_hi[idx] = h;
        g_WT_lo[idx] = __float2bfloat16(x - __bfloat162float(h));
    }
}

__global__ void __launch_bounds__(128) decproj_kernel(
    const float* __restrict__ dh, const float* __restrict__ W,
    const float* __restrict__ bias)
{
    const int n = blockIdx.x * 128 + threadIdx.x;
    const int b = blockIdx.y;
    const int k0 = blockIdx.z * 128;
    __shared__ float sh[128];
    sh[threadIdx.x] = dh[b * K_DIM + k0 + threadIdx.x];
    __syncthreads();
    float acc = (blockIdx.z == 0) ? bias[n] : 0.f;
#pragma unroll 8
    for (int k = 0; k < 128; ++k)
        acc += sh[k] * W[(size_t)(k0 + k) * N_DIM + n];
    atomicAdd(&g_decproj[b * N_DIM + n], acc);
}

// ---------------------------------------------------------------------------
// Main: split-bf16 HMMA GEMM, 4-stage cp.async pipeline, fused tanh/v epilogue
// CTA 128x128, 512 threads / 16 warps (4m x 4n), warp tile 32x32, KC=32.
// 1 CTA/SM, ~85 regs/thread (no spills), 128 KB smem.
// ---------------------------------------------------------------------------
__global__ void __launch_bounds__(512, 1) energy_kernel(const float* __restrict__ v)
{
    extern __shared__ char smem[];
    const uint32_t sb = smem_u32(smem);
    const int tid  = threadIdx.x;
    const int lane = tid & 31;
    const int w    = tid >> 5;
    const int wm   = w >> 2;          // 0..3 (m group of 32 rows)
    const int wn   = w & 3;           // 0..3 (n group of 32 cols)
    const int m0   = blockIdx.y * MT;
    const int n0   = blockIdx.x * NT;
    const int b    = m0 >> 10;

    // copy assignments: 4 threads/row; q selects hi(q<2)/lo(q>=2) and 32B quarter
    const int lrow = tid >> 2;
    const int q    = tid & 3;
    const __nv_bfloat16* aSrc =
        (q < 2 ? g_enc_hi : g_enc_lo) + (size_t)(m0 + lrow) * K_DIM + (q & 1) * 16;
    const __nv_bfloat16* bSrc =
        (q < 2 ? g_WT_hi : g_WT_lo) + (size_t)(n0 + lrow) * K_DIM + (q & 1) * 16;
    const uint32_t dRow = lrow * 128 + q * 32;   // pre-swizzle byte offset

    // ldmatrix lane addressing
    const int lr  = lane & 15;
    const int lkh = (lane >> 4) * 16;

    float acc[2][4][4];
#pragma unroll
    for (int mf = 0; mf < 2; ++mf)
#pragma unroll
        for (int nf = 0; nf < 4; ++nf)
#pragma unroll
            for (int e = 0; e < 4; ++e) acc[mf][nf][e] = 0.f;

#define ISSUE_CHUNK(c) do {                                                   \
    const uint32_t st = sb + ((c) % NSTAGES) * STAGE_SZ;                      \
    const int gk = (c) * KC;                                                  \
    const uint32_t s0 = sw128(dRow);                                          \
    const uint32_t s1 = sw128(dRow + 16);                                     \
    CP16(st + SA_OFF + s0, aSrc + gk);                                        \
    CP16(st + SA_OFF + s1, aSrc + gk + 8);                                    \
    CP16(st + SB_OFF + s0, bSrc + gk);                                        \
    CP16(st + SB_OFF + s1, bSrc + gk + 8);                                    \
} while (0)

    // prologue: stages 0..2 in flight
    ISSUE_CHUNK(0); CP_COMMIT();
    ISSUE_CHUNK(1); CP_COMMIT();
    ISSUE_CHUNK(2); CP_COMMIT();

    for (int c = 0; c < NCHUNK; ++c) {
        CP_WAIT2();
        __syncthreads();
        if (c + 3 < NCHUNK) ISSUE_CHUNK(c + 3);
        CP_COMMIT();

        const uint32_t st = sb + (c % NSTAGES) * STAGE_SZ;
#pragma unroll
        for (int ks = 0; ks < 2; ++ks) {
            const int kb = ks * 32 + lkh;
            uint32_t Ah[2][4], Al[2][4], Bh[2][4], Bl[2][4];
#pragma unroll
            for (int mf = 0; mf < 2; ++mf)
                LDSM4(Ah[mf], st + SA_OFF + sw128((wm * 32 + mf * 16 + lr) * 128 + kb));
#pragma unroll
            for (int g = 0; g < 2; ++g)
                LDSM4(Bh[g], st + SB_OFF + sw128((wn * 32 + g * 16 + lr) * 128 + kb));
            // hh
#pragma unroll
            for (int mf = 0; mf < 2; ++mf)
#pragma unroll
                for (int g = 0; g < 2; ++g) {
                    MMA16816(acc[mf][g * 2 + 0], Ah[mf], Bh[g][0], Bh[g][2]);
                    MMA16816(acc[mf][g * 2 + 1], Ah[mf], Bh[g][1], Bh[g][3]);
                }
            // hl (Ah reused)
#pragma unroll
            for (int g = 0; g < 2; ++g)
                LDSM4(Bl[g], st + SB_OFF + sw128((wn * 32 + g * 16 + lr) * 128 + 64 + kb));
#pragma unroll
            for (int mf = 0; mf < 2; ++mf)
#pragma unroll
                for (int g = 0; g < 2; ++g) {
                    MMA16816(acc[mf][g * 2 + 0], Ah[mf], Bl[g][0], Bl[g][2]);
                    MMA16816(acc[mf][g * 2 + 1], Ah[mf], Bl[g][1], Bl[g][3]);
                }
            // lh (Bh reused)
#pragma unroll
            for (int mf = 0; mf < 2; ++mf)
                LDSM4(Al[mf], st + SA_OFF + sw128((wm * 32 + mf * 16 + lr) * 128 + 64 + kb));
#pragma unroll
            for (int mf = 0; mf < 2; ++mf)
#pragma unroll
                for (int g = 0; g < 2; ++g) {
                    MMA16816(acc[mf][g * 2 + 0], Al[mf], Bh[g][0], Bh[g][2]);
                    MMA16816(acc[mf][g * 2 + 1], Al[mf], Bh[g][1], Bh[g][3]);
                }
        }
    }
#undef ISSUE_CHUNK
    CP_WAIT0();

    // ---- epilogue: rowsum += tanh(acc + dec[n]) * v[n]; warp-reduce; atomic ----
    const int qrow = lane >> 2;
    const int qcol = (lane & 3) * 2;
    float rs[2][2];
#pragma unroll
    for (int mf = 0; mf < 2; ++mf) { rs[mf][0] = 0.f; rs[mf][1] = 0.f; }
#pragma unroll
    for (int nf = 0; nf < 4; ++nf) {
        const int col = n0 + wn * 32 + nf * 8 + qcol;
        const float v0 = v[col], v1 = v[col + 1];
        const float d0 = g_decproj[b * N_DIM + col];
        const float d1 = g_decproj[b * N_DIM + col + 1];
#pragma unroll
        for (int mf = 0; mf < 2; ++mf) {
            rs[mf][0] += fast_tanh(acc[mf][nf][0] + d0) * v0
                       + fast_tanh(acc[mf][nf][1] + d1) * v1;
            rs[mf][1] += fast_tanh(acc[mf][nf][2] + d0) * v0
                       + fast_tanh(acc[mf][nf][3] + d1) * v1;
        }
    }
#pragma unroll
    for (int mf = 0; mf < 2; ++mf)
#pragma unroll
        for (int h = 0; h < 2; ++h) {
            float s = rs[mf][h];
            s += __shfl_xor_sync(0xffffffffu, s, 1);
            s += __shfl_xor_sync(0xffffffffu, s, 2);
            if ((lane & 3) == 0)
                atomicAdd(&g_logits[m0 + wm * 32 + mf * 16 + h * 8 + qrow], s);
        }
}

// ---------------------------------------------------------------------------
// Softmax over S per batch row
// ---------------------------------------------------------------------------
__global__ void __launch_bounds__(256) softmax_kernel(float* __restrict__ out)
{
    const int b = blockIdx.x, tid = threadIdx.x;
    __shared__ float sm[256];
    float vals[4];
    float m = -1e30f;
#pragma unroll
    for (int q = 0; q < 4; ++q) {
        vals[q] = g_logits[b * S_SZ + tid + 256 * q];
        m = fmaxf(m, vals[q]);
    }
    sm[tid] = m;
    __syncthreads();
    for (int s = 128; s > 0; s >>= 1) {
        if (tid < s) sm[tid] = fmaxf(sm[tid], sm[tid + s]);
        __syncthreads();
    }
    const float mx = sm[0];
    __syncthreads();
    float e[4], ssum = 0.f;
#pragma unroll
    for (int q = 0; q < 4; ++q) { e[q] = expf(vals[q] - mx); ssum += e[q]; }
    sm[tid] = ssum;
    __syncthreads();
    for (int s = 128; s > 0; s >>= 1) {
        if (tid < s) sm[tid] += sm[tid + s];
        __syncthreads();
    }
    const float inv = 1.f / sm[0];
#pragma unroll
    for (int q = 0; q < 4; ++q) out[b * S_SZ + tid + 256 * q] = e[q] * inv;
}

// ---------------------------------------------------------------------------
extern "C" void kernel_launch(void* const* d_in, const int* in_sizes, int n_in,
                              void* d_out, int out_size)
{
    const float* dh   = (const float*)d_in[0];
    const float* enc  = (const float*)d_in[1];
    const float* W    = (const float*)d_in[2];
    const float* bias = (const float*)d_in[3];
    const float* v    = (const float*)d_in[4];
    float* out = (float*)d_out;

    cudaFuncSetAttribute(energy_kernel,
                         cudaFuncAttributeMaxDynamicSharedMemorySize, SMEM_SZ);

    zero_kernel<<<128, 256>>>();
    prep_enc<<<(int)(((size_t)M_TOT * K_DIM) / 4 / 256), 256>>>(enc);
    prep_wt<<<dim3(32, 32), dim3(32, 8)>>>(W);
    decproj_kernel<<<dim3(8, 32, 8), 128>>>(dh, W, bias);
    energy_kernel<<<dim3(N_DIM / NT, M_TOT / MT), 512, SMEM_SZ>>>(v);
    softmax_kernel<<<B_SZ, 256>>>(out);
}